// round 8
// baseline (speedup 1.0000x reference)
#include <cuda_runtime.h>

#define B 256
#define S 2048
#define V 100000
#define E 128

#define NPROJ 296                  // proj role blocks (2/SM worth of streaming)
#define NPOOL B                    // one pool block per batch row
#define GRID  (NPROJ + NPOOL)      // 552 <= wave-1 capacity 592 @ 4 blk/SM
#define PWARPS (NPROJ * 8)         // 2368 streaming warps
#define NJOBS (V / 8)              // 12500 8-row jobs (V % 8 == 0)

// __device__ scratch (no cudaMalloc allowed). Zero-initialized at load.
__device__ float g_proj[V];
__device__ unsigned int g_done;    // proj-complete flag
__device__ unsigned int g_pcnt;    // finished proj blocks
__device__ unsigned int g_qcnt;    // finished pool blocks (last one resets)

__global__ void __launch_bounds__(256, 4)
fused_kernel(const int* __restrict__ text, const int* __restrict__ lengths,
             const float* __restrict__ emb, const float* __restrict__ fc_w,
             const float* __restrict__ fc_b, float* __restrict__ out)
{
    const int tid  = threadIdx.x;
    const int lane = tid & 31;
    const int warp = tid >> 5;

    if (blockIdx.x < NPROJ) {
        // ================= PROJ role: stream emb, write g_proj =================
        const int c = lane & 7;       // 16B chunk within the 128B line
        const int r = lane >> 3;      // row within quad (0..3)
        const int gw = blockIdx.x * 8 + warp;

        const float4* e4 = reinterpret_cast<const float4*>(emb);
        const float4* wp = reinterpret_cast<const float4*>(fc_w);
        const float4 w0 = wp[c +  0];
        const float4 w1 = wp[c +  8];
        const float4 w2 = wp[c + 16];
        const float4 w3 = wp[c + 24];

        for (int g = gw; g < NJOBS; g += PWARPS) {
            const int base = g * 8;                      // first of 8 rows
            // float4 index of (row, line j, chunk c) = row*32 + j*8 + c  (fits 32-bit)
            const unsigned iA = (unsigned)(base     + r) * 32u + c;
            const unsigned iB = (unsigned)(base + 4 + r) * 32u + c;

            // 8 independent full-line loads, front-batched; evict-first (read-once)
            float4 a0 = __ldcs(e4 + iA +  0);
            float4 a1 = __ldcs(e4 + iA +  8);
            float4 a2 = __ldcs(e4 + iA + 16);
            float4 a3 = __ldcs(e4 + iA + 24);
            float4 b0 = __ldcs(e4 + iB +  0);
            float4 b1 = __ldcs(e4 + iB +  8);
            float4 b2 = __ldcs(e4 + iB + 16);
            float4 b3 = __ldcs(e4 + iB + 24);

            float sa = 0.f, sb = 0.f;
            sa = fmaf(a0.x,w0.x,sa); sa = fmaf(a0.y,w0.y,sa); sa = fmaf(a0.z,w0.z,sa); sa = fmaf(a0.w,w0.w,sa);
            sa = fmaf(a1.x,w1.x,sa); sa = fmaf(a1.y,w1.y,sa); sa = fmaf(a1.z,w1.z,sa); sa = fmaf(a1.w,w1.w,sa);
            sa = fmaf(a2.x,w2.x,sa); sa = fmaf(a2.y,w2.y,sa); sa = fmaf(a2.z,w2.z,sa); sa = fmaf(a2.w,w2.w,sa);
            sa = fmaf(a3.x,w3.x,sa); sa = fmaf(a3.y,w3.y,sa); sa = fmaf(a3.z,w3.z,sa); sa = fmaf(a3.w,w3.w,sa);
            sb = fmaf(b0.x,w0.x,sb); sb = fmaf(b0.y,w0.y,sb); sb = fmaf(b0.z,w0.z,sb); sb = fmaf(b0.w,w0.w,sb);
            sb = fmaf(b1.x,w1.x,sb); sb = fmaf(b1.y,w1.y,sb); sb = fmaf(b1.z,w1.z,sb); sb = fmaf(b1.w,w1.w,sb);
            sb = fmaf(b2.x,w2.x,sb); sb = fmaf(b2.y,w2.y,sb); sb = fmaf(b2.z,w2.z,sb); sb = fmaf(b2.w,w2.w,sb);
            sb = fmaf(b3.x,w3.x,sb); sb = fmaf(b3.y,w3.y,sb); sb = fmaf(b3.z,w3.z,sb); sb = fmaf(b3.w,w3.w,sb);

            // reduce across 8 c-lanes (both quads simultaneously)
            sa += __shfl_xor_sync(0xffffffffu, sa, 1); sb += __shfl_xor_sync(0xffffffffu, sb, 1);
            sa += __shfl_xor_sync(0xffffffffu, sa, 2); sb += __shfl_xor_sync(0xffffffffu, sb, 2);
            sa += __shfl_xor_sync(0xffffffffu, sa, 4); sb += __shfl_xor_sync(0xffffffffu, sb, 4);

            if (c == 0) {
                g_proj[base     + r] = sa;
                g_proj[base + 4 + r] = sb;
            }
        }

        // block done -> release: last proj block publishes the flag
        __syncthreads();
        if (tid == 0) {
            __threadfence();
            unsigned int old = atomicAdd(&g_pcnt, 1u);
            if (old == NPROJ - 1u)
                atomicExch(&g_done, 1u);        // release (fence above orders stores)
        }
    } else {
        // ================= POOL role: one block per batch row =================
        __shared__ float sred[8];
        const int b = blockIdx.x - NPROJ;
        const int len = lengths[b];

        // preload my 8 tokens BEFORE the wait — hidden under proj streaming
        const int4* row = reinterpret_cast<const int4*>(text + (size_t)b * S);
        int4 t0 = row[tid * 2 + 0];
        int4 t1 = row[tid * 2 + 1];
        const int s = tid * 8;

        // wait for proj completion (single spinner per block, gentle)
        if (tid == 0) {
            while (atomicAdd(&g_done, 0u) == 0u) __nanosleep(128);
        }
        __syncthreads();
        __threadfence();   // acquire: order g_proj reads after the flag

        float acc = 0.0f;
        if (s + 0 < len) acc += __ldcg(&g_proj[t0.x]);
        if (s + 1 < len) acc += __ldcg(&g_proj[t0.y]);
        if (s + 2 < len) acc += __ldcg(&g_proj[t0.z]);
        if (s + 3 < len) acc += __ldcg(&g_proj[t0.w]);
        if (s + 4 < len) acc += __ldcg(&g_proj[t1.x]);
        if (s + 5 < len) acc += __ldcg(&g_proj[t1.y]);
        if (s + 6 < len) acc += __ldcg(&g_proj[t1.z]);
        if (s + 7 < len) acc += __ldcg(&g_proj[t1.w]);

        #pragma unroll
        for (int off = 16; off; off >>= 1)
            acc += __shfl_xor_sync(0xffffffffu, acc, off);
        if (lane == 0) sred[warp] = acc;
        __syncthreads();
        if (warp == 0) {
            float v = (lane < 8) ? sred[lane] : 0.0f;
            #pragma unroll
            for (int off = 4; off; off >>= 1)
                v += __shfl_xor_sync(0xffffffffu, v, off);
            if (lane == 0)
                out[b] = v / (float)len + fc_b[0];
        }

        // last pool block resets counters for the next graph replay
        __syncthreads();
        if (tid == 0) {
            unsigned int old = atomicAdd(&g_qcnt, 1u);
            if (old == NPOOL - 1u) {
                g_pcnt = 0u;
                g_qcnt = 0u;
                atomicExch(&g_done, 0u);
            }
        }
    }
}

extern "C" void kernel_launch(void* const* d_in, const int* in_sizes, int n_in,
                              void* d_out, int out_size) {
    const int*   text    = (const int*)d_in[0];
    const int*   lengths = (const int*)d_in[1];
    const float* emb     = (const float*)d_in[2];
    const float* fc_w    = (const float*)d_in[3];
    const float* fc_b    = (const float*)d_in[4];
    float* out = (float*)d_out;

    fused_kernel<<<GRID, 256>>>(text, lengths, emb, fc_w, fc_b, out);
}

// round 9
// speedup vs baseline: 1.1805x; 1.1805x over previous
#include <cuda_runtime.h>

#define B 256
#define S 2048
#define V 100000
#define E 128

#define PBLK 592                 // 4 resident blocks/SM x 148 SMs (56 regs fits 64 budget)
#define NWARPS (PBLK * 8)        // 4736 streaming warps
#define NJOBS (V / 8)            // 12500 8-row jobs (V % 8 == 0)

// __device__ scratch (no cudaMalloc allowed). Zero-initialized at load.
__device__ float g_proj[V];          // proj[v] = dot(emb[v], fc_w)
__device__ float g_part[B * 2];      // 2 partials per batch row
__device__ unsigned int g_cnt[B];    // tickets (last arriver resets to 0)

// proj: persistent streaming, 4 blocks/SM (32 warps/SM). Each warp iterates
// 8-row (4KB) jobs: 8 front-batched full-line LDG.128s (__ldcs: evict-first,
// emb is read-once), lane c = 16B chunk, lane r = row-in-quad. 6 shuffles
// reduce all 8 rows. Doubling resident warps vs R7 doubles iteration overlap.
__global__ void __launch_bounds__(256, 4) proj_kernel(const float* __restrict__ emb,
                                                      const float* __restrict__ fc_w) {
    const int lane = threadIdx.x & 31;
    const int warp = threadIdx.x >> 5;
    const int c = lane & 7;
    const int r = lane >> 3;
    const int gw = blockIdx.x * 8 + warp;

    const float4* e4 = reinterpret_cast<const float4*>(emb);
    const float4* wp = reinterpret_cast<const float4*>(fc_w);
    const float4 w0 = wp[c +  0];
    const float4 w1 = wp[c +  8];
    const float4 w2 = wp[c + 16];
    const float4 w3 = wp[c + 24];

    for (int g = gw; g < NJOBS; g += NWARPS) {
        const int base = g * 8;
        const unsigned iA = (unsigned)(base     + r) * 32u + c;
        const unsigned iB = (unsigned)(base + 4 + r) * 32u + c;

        float4 a0 = __ldcs(e4 + iA +  0);
        float4 a1 = __ldcs(e4 + iA +  8);
        float4 a2 = __ldcs(e4 + iA + 16);
        float4 a3 = __ldcs(e4 + iA + 24);
        float4 b0 = __ldcs(e4 + iB +  0);
        float4 b1 = __ldcs(e4 + iB +  8);
        float4 b2 = __ldcs(e4 + iB + 16);
        float4 b3 = __ldcs(e4 + iB + 24);

        float sa = 0.f, sb = 0.f;
        sa = fmaf(a0.x,w0.x,sa); sa = fmaf(a0.y,w0.y,sa); sa = fmaf(a0.z,w0.z,sa); sa = fmaf(a0.w,w0.w,sa);
        sa = fmaf(a1.x,w1.x,sa); sa = fmaf(a1.y,w1.y,sa); sa = fmaf(a1.z,w1.z,sa); sa = fmaf(a1.w,w1.w,sa);
        sa = fmaf(a2.x,w2.x,sa); sa = fmaf(a2.y,w2.y,sa); sa = fmaf(a2.z,w2.z,sa); sa = fmaf(a2.w,w2.w,sa);
        sa = fmaf(a3.x,w3.x,sa); sa = fmaf(a3.y,w3.y,sa); sa = fmaf(a3.z,w3.z,sa); sa = fmaf(a3.w,w3.w,sa);
        sb = fmaf(b0.x,w0.x,sb); sb = fmaf(b0.y,w0.y,sb); sb = fmaf(b0.z,w0.z,sb); sb = fmaf(b0.w,w0.w,sb);
        sb = fmaf(b1.x,w1.x,sb); sb = fmaf(b1.y,w1.y,sb); sb = fmaf(b1.z,w1.z,sb); sb = fmaf(b1.w,w1.w,sb);
        sb = fmaf(b2.x,w2.x,sb); sb = fmaf(b2.y,w2.y,sb); sb = fmaf(b2.z,w2.z,sb); sb = fmaf(b2.w,w2.w,sb);
        sb = fmaf(b3.x,w3.x,sb); sb = fmaf(b3.y,w3.y,sb); sb = fmaf(b3.z,w3.z,sb); sb = fmaf(b3.w,w3.w,sb);

        sa += __shfl_xor_sync(0xffffffffu, sa, 1); sb += __shfl_xor_sync(0xffffffffu, sb, 1);
        sa += __shfl_xor_sync(0xffffffffu, sa, 2); sb += __shfl_xor_sync(0xffffffffu, sb, 2);
        sa += __shfl_xor_sync(0xffffffffu, sa, 4); sb += __shfl_xor_sync(0xffffffffu, sb, 4);

        if (c == 0) {
            g_proj[base     + r] = sa;
            g_proj[base + 4 + r] = sb;
        }
    }
}

// pool: 512 blocks x 256 thr; block (b = bid>>1, h = bid&1) handles tokens
// [h*1024, h*1024+1024): one int4 (4 tokens) per thread, single gather round.
// Ticket finalize: last of the 2 blocks for row b combines partials, writes
// out[b], resets the ticket (device globals start 0 -> replay-deterministic).
__global__ void __launch_bounds__(256) pool_kernel(const int* __restrict__ text,
                                                   const int* __restrict__ lengths,
                                                   const float* __restrict__ fc_b,
                                                   float* __restrict__ out) {
    __shared__ float sred[8];
    const int bid = blockIdx.x;
    const int b   = bid >> 1;
    const int h   = bid & 1;
    const int tid = threadIdx.x;
    const int len = lengths[b];

    const int base = h * 1024;
    int4 t = reinterpret_cast<const int4*>(text + (size_t)b * S + base)[tid];
    const int s = base + tid * 4;

    float acc = 0.0f;
    if (s + 0 < len) acc += g_proj[t.x];
    if (s + 1 < len) acc += g_proj[t.y];
    if (s + 2 < len) acc += g_proj[t.z];
    if (s + 3 < len) acc += g_proj[t.w];

    #pragma unroll
    for (int off = 16; off; off >>= 1)
        acc += __shfl_xor_sync(0xffffffffu, acc, off);
    const int lane = tid & 31, warp = tid >> 5;
    if (lane == 0) sred[warp] = acc;
    __syncthreads();

    if (tid == 0) {
        float part = sred[0] + sred[1] + sred[2] + sred[3]
                   + sred[4] + sred[5] + sred[6] + sred[7];
        g_part[bid] = part;
        __threadfence();
        unsigned int old = atomicAdd(&g_cnt[b], 1u);
        if (old == 1u) {                    // last of the 2 blocks for row b
            __threadfence();
            float v = __ldcg(&g_part[b * 2 + 0]) + __ldcg(&g_part[b * 2 + 1]);
            out[b] = v / (float)len + fc_b[0];
            g_cnt[b] = 0u;                  // re-arm for the next graph replay
        }
    }
}

extern "C" void kernel_launch(void* const* d_in, const int* in_sizes, int n_in,
                              void* d_out, int out_size) {
    const int*   text    = (const int*)d_in[0];
    const int*   lengths = (const int*)d_in[1];
    const float* emb     = (const float*)d_in[2];
    const float* fc_w    = (const float*)d_in[3];
    const float* fc_b    = (const float*)d_in[4];
    float* out = (float*)d_out;

    proj_kernel<<<PBLK, 256>>>(emb, fc_w);
    pool_kernel<<<B * 2, 256>>>(text, lengths, fc_b, out);
}